// round 16
// baseline (speedup 1.0000x reference)
#include <cuda_runtime.h>
#include <cuda_bf16.h>
#include <cstdint>
#include <cstddef>

// Residual VQ, round 16: 2 CTAs/SM. R13's mbarrier-handoff ring + R7's proven
// 32x32 warp geometry, halved per CTA: MC=64 rows, 256 threads (8 warps,
// warp grid 2x4), BN=128, smem 112KB/CTA -> 2 co-resident CTAs per SM.
// Grid 256 covers all 148 SMs in one wave; co-resident CTAs overlap each
// other's depth-end tails and mainloop stalls on the tensor pipe (R13 pipe
// idle 57%). Candidate scheme (top-2/thread -> 32/row -> top-8 -> exact fp32
// rescore) unchanged.

#define NTOK     16384
#define DIM      512
#define KS       4096
#define MC       64
#define THREADS  256
#define NWARP    8
#define BN       128               // codes per CTA tile
#define BK       64                // k per unit
#define NTILES   (KS / BN)         // 32
#define NCHUNK   (DIM / BK)        // 8
#define UNITS    (NTILES * NCHUNK) // 256
#define BTILE_BYTES (BN * BK * 2)  // 16384
#define NBUF     3
#define A_BYTES  (MC * DIM * 2)    // 65536

__device__ float         g_res[(size_t)NTOK * DIM];   // fp32 residual master
__device__ __nv_bfloat16 g_cbh[(size_t)KS * DIM];     // bf16 codebook

// ---------------------------------------------------------------------------
static __device__ __forceinline__ uint32_t smem_u32(const void* p) {
    return (uint32_t)__cvta_generic_to_shared(p);
}
static __device__ __forceinline__ void ldsm4(uint32_t* r, uint32_t a) {
    asm volatile("ldmatrix.sync.aligned.m8n8.x4.shared.b16 {%0,%1,%2,%3}, [%4];"
                 : "=r"(r[0]), "=r"(r[1]), "=r"(r[2]), "=r"(r[3]) : "r"(a));
}
static __device__ __forceinline__ void mma16816(float* c, const uint32_t* a,
                                                const uint32_t* b) {
    asm volatile("mma.sync.aligned.m16n8k16.row.col.f32.bf16.bf16.f32 "
                 "{%0,%1,%2,%3}, {%4,%5,%6,%7}, {%8,%9}, {%0,%1,%2,%3};"
                 : "+f"(c[0]), "+f"(c[1]), "+f"(c[2]), "+f"(c[3])
                 : "r"(a[0]), "r"(a[1]), "r"(a[2]), "r"(a[3]),
                   "r"(b[0]), "r"(b[1]));
}
static __device__ __forceinline__ void cp16(uint32_t dst, const void* src) {
    asm volatile("cp.async.cg.shared.global [%0], [%1], 16;" :: "r"(dst), "l"(src));
}
static __device__ __forceinline__ void mbar_init(uint32_t a, uint32_t cnt) {
    asm volatile("mbarrier.init.shared.b64 [%0], %1;" :: "r"(a), "r"(cnt) : "memory");
}
static __device__ __forceinline__ void mbar_arrive(uint32_t a) {
    asm volatile("mbarrier.arrive.shared.b64 _, [%0];" :: "r"(a) : "memory");
}
// Arrive on mbar when all of this thread's prior cp.asyncs have completed.
static __device__ __forceinline__ void cpasync_mbar_arrive(uint32_t a) {
    asm volatile("cp.async.mbarrier.arrive.noinc.shared.b64 [%0];" :: "r"(a) : "memory");
}
static __device__ __forceinline__ void mbar_wait(uint32_t a, uint32_t parity) {
    uint32_t done;
    asm volatile("{\n\t.reg .pred p;\n\t"
                 "mbarrier.try_wait.parity.acquire.cta.shared::cta.b64 p, [%1], %2;\n\t"
                 "selp.b32 %0, 1, 0, p;\n\t}"
                 : "=r"(done) : "r"(a), "r"(parity) : "memory");
    if (!done) {
        asm volatile("{\n\t.reg .pred P1;\n\t"
                     "WL%=:\n\t"
                     "mbarrier.try_wait.parity.acquire.cta.shared::cta.b64 P1, [%0], %1, 0x989680;\n\t"
                     "@P1 bra.uni WD%=;\n\tbra.uni WL%=;\n\tWD%=:\n\t}"
                     :: "r"(a), "r"(parity) : "memory");
    }
}

static __device__ __forceinline__ uint32_t pack_bf2(float a, float b) {
    __nv_bfloat162 h = __floats2bfloat162_rn(a, b);
    return *reinterpret_cast<uint32_t*>(&h);
}

// ---------------------------------------------------------------------------
__global__ void pack_cb_kernel(const float* __restrict__ cb) {
    const size_t i = ((size_t)blockIdx.x * 256 + threadIdx.x) * 4;
    const float4 v = *reinterpret_cast<const float4*>(cb + i);
    uint2 o;
    o.x = pack_bf2(v.x, v.y);
    o.y = pack_bf2(v.z, v.w);
    *reinterpret_cast<uint2*>(&g_cbh[i]) = o;
}

// ---------------------------------------------------------------------------
// main: grid 256 CTAs x 256 threads, 2 CTAs/SM.
// dyn smem: A 64KB (bf16 residual, swizzled 1KB rows) + 3 x 16KB B ring.
// Candidate arrays use the ring buffer that is idle at each depth end.
// ---------------------------------------------------------------------------
__global__ void __launch_bounds__(THREADS, 2)
rvq_mma_kernel(const float* __restrict__ x, const float* __restrict__ cb,
               const int* __restrict__ depth_ptr, float* __restrict__ out) {
    extern __shared__ __align__(1024) unsigned char raw[];
    unsigned char* sAp = raw;                        // [64 rows][512 bf16] swizzled
    const uint32_t sA  = smem_u32(sAp);
    const uint32_t sB0 = smem_u32(raw + A_BYTES);    // 3 ring buffers

    __shared__ __align__(8) unsigned long long s_mbar[6];  // full0..2, empty0..2

    const int tid  = threadIdx.x;
    const int warp = tid >> 5;
    const int lane = tid & 31;
    const int wm   = warp >> 2;     // row group: rows wm*32 .. +31 (0..1)
    const int wn   = warp & 3;      // code group within B tile: wn*32 .. +31
    const size_t row0 = (size_t)blockIdx.x * MC;

    uint32_t mb_full[3], mb_empty[3];
#pragma unroll
    for (int b = 0; b < 3; b++) {
        mb_full[b]  = smem_u32(&s_mbar[b]);
        mb_empty[b] = smem_u32(&s_mbar[3 + b]);
    }

    int depth = 4;
    if (depth_ptr) {
        const int dd = *depth_ptr;
        if (dd >= 0 && dd <= 8) depth = dd;
    }
    const int total = depth * UNITS;

    if (tid == 0) {
#pragma unroll
        for (int b = 0; b < 3; b++) {
            mbar_init(mb_full[b], THREADS);   // one cp.async arrive per thread
            mbar_init(mb_empty[b], NWARP);    // one arrive per consumer warp
        }
    }

    // ---- init: residual = x (fp32 global) + bf16 A tile in smem ----
    for (int e = tid; e < MC * 64; e += THREADS) {
        const int row = e >> 6, c = e & 63;      // c = 16B chunk (8 floats)
        const float4* src = reinterpret_cast<const float4*>(x + (row0 + row) * DIM + c * 8);
        const float4 v0 = src[0], v1 = src[1];
        float4* dres = reinterpret_cast<float4*>(g_res + (row0 + row) * DIM + c * 8);
        dres[0] = v0; dres[1] = v1;
        uint4 pk;
        pk.x = pack_bf2(v0.x, v0.y); pk.y = pack_bf2(v0.z, v0.w);
        pk.z = pack_bf2(v1.x, v1.y); pk.w = pack_bf2(v1.z, v1.w);
        *reinterpret_cast<uint4*>(sAp + row * 1024 + ((c ^ (row & 7)) << 4)) = pk;
    }
    __syncthreads();   // publishes mbarrier init + A tile

    // Fill global unit G (4 x 16B cp.async per thread) with mbarrier handoff.
    auto fillg = [&](int G) {
        const int b2 = G % NBUF;
        const int r2 = G / NBUF;
        mbar_wait(mb_empty[b2], (uint32_t)((r2 & 1) ^ 1));  // prior consumers done
        const int u2 = G % UNITS;
        const int nt = u2 >> 3, kc = u2 & 7;
        const uint32_t dst = sB0 + (uint32_t)b2 * BTILE_BYTES;
        const __nv_bfloat16* src = g_cbh + (size_t)(nt * BN) * DIM + kc * BK;
#pragma unroll
        for (int i = 0; i < 4; i++) {
            const int e = tid + THREADS * i;
            const int rowb = e >> 3, c = e & 7;
            cp16(dst + rowb * 128 + ((c ^ (rowb & 7)) << 4),
                 src + (size_t)rowb * DIM + c * 8);
        }
        cpasync_mbar_arrive(mb_full[b2]);
    };

    // prologue: stage first two units
    fillg(0);
    if (total > 1) fillg(1);

    // per-thread fragment address constants
    const int lm = lane & 15, lh = lane >> 4;
    const int axor = lm & 7;
    uint32_t cAm[2];
#pragma unroll
    for (int mi = 0; mi < 2; mi++)
        cAm[mi] = sA + (uint32_t)(wm * 32 + mi * 16 + lm) * 1024;
    const int grp = lane >> 3, lrow = lane & 7, kpar = grp & 1;
    const int rowoff = ((grp >> 1) << 3) + lrow;
    const int bxor = lrow;

    for (int d = 0; d < depth; d++) {
        float acc[2][4][4];
#pragma unroll
        for (int mi = 0; mi < 2; mi++)
#pragma unroll
            for (int ni = 0; ni < 4; ni++)
#pragma unroll
                for (int j = 0; j < 4; j++) acc[mi][ni][j] = 0.0f;

        float t1v[4], t2v[4]; int t1i[4], t2i[4];
#pragma unroll
        for (int r = 0; r < 4; r++) {
            t1v[r] = -3.0e38f; t2v[r] = -3.0e38f;
            t1i[r] = 0x7fffffff; t2i[r] = 0x7fffffff;
        }

        for (int u = 0; u < UNITS; u++) {
            const int g  = d * UNITS + u;
            const int b  = g % NBUF;
            const int nt = u >> 3, kc = u & 7;

            mbar_wait(mb_full[b], (uint32_t)((g / NBUF) & 1));  // tile resident

            const uint32_t sB = sB0 + (uint32_t)b * BTILE_BYTES;
            uint32_t cBn[2];
#pragma unroll
            for (int nb = 0; nb < 2; nb++)
                cBn[nb] = sB + (uint32_t)(wn * 32 + nb * 16 + rowoff) * 128;

#pragma unroll
            for (int ks = 0; ks < 4; ks++) {
                uint32_t a[2][4], bfr[2][4];
                const int ck = kc * 8 + ks * 2 + lh;          // 8 chunks per unit
                const uint32_t aoff = (uint32_t)((ck ^ axor) << 4);
#pragma unroll
                for (int mi = 0; mi < 2; mi++) ldsm4(a[mi], cAm[mi] + aoff);
                const uint32_t boff = (uint32_t)(((ks * 2 + kpar) ^ bxor) << 4);
#pragma unroll
                for (int nb = 0; nb < 2; nb++) ldsm4(bfr[nb], cBn[nb] + boff);
#pragma unroll
                for (int mi = 0; mi < 2; mi++)
#pragma unroll
                    for (int nb = 0; nb < 2; nb++) {
                        mma16816(acc[mi][nb * 2 + 0], a[mi], bfr[nb] + 0);
                        mma16816(acc[mi][nb * 2 + 1], a[mi], bfr[nb] + 2);
                    }
            }

            if (lane == 0) mbar_arrive(mb_empty[b]);   // this warp done with buffer

            if (kc == NCHUNK - 1) {
                // ---- N-tile epilogue: update per-row top-2, reset accs ----
                const int cb0 = nt * BN + wn * 32 + 2 * (lane & 3);
#pragma unroll
                for (int mi = 0; mi < 2; mi++)
#pragma unroll
                    for (int rh = 0; rh < 2; rh++) {
                        const int ri = mi * 2 + rh;
#pragma unroll
                        for (int ni = 0; ni < 4; ni++)
#pragma unroll
                            for (int j = 0; j < 2; j++) {
                                const float v = acc[mi][ni][rh * 2 + j];
                                const int  ix = cb0 + ni * 8 + j;
                                if (v > t1v[ri]) {
                                    t2v[ri] = t1v[ri]; t2i[ri] = t1i[ri];
                                    t1v[ri] = v;       t1i[ri] = ix;
                                } else if (v > t2v[ri]) {
                                    t2v[ri] = v; t2i[ri] = ix;
                                }
                            }
#pragma unroll
                        for (int ni = 0; ni < 4; ni++) {
                            acc[mi][ni][rh * 2 + 0] = 0.0f;
                            acc[mi][ni][rh * 2 + 1] = 0.0f;
                        }
                    }
            }

            const int G2 = g + 2;
            if (G2 < total) fillg(G2);     // refill two units ahead (R13 order)
        }

        __syncthreads();   // all warps past last compute; bfree buffer idle

        // candidate arrays live in the ring buffer NOT being refilled now
        const int bfree = (d * UNITS + UNITS - 1) % NBUF;
        float* s_cv = reinterpret_cast<float*>(raw + A_BYTES + (size_t)bfree * BTILE_BYTES);
        int*   s_ci = reinterpret_cast<int*>(raw + A_BYTES + (size_t)bfree * BTILE_BYTES + 8192);

        // ---- stash 32 candidates per row ----
#pragma unroll
        for (int mi = 0; mi < 2; mi++)
#pragma unroll
            for (int rh = 0; rh < 2; rh++) {
                const int ri  = mi * 2 + rh;
                const int row = wm * 32 + mi * 16 + rh * 8 + (lane >> 2);
                const int sb  = wn * 8 + (lane & 3) * 2;
                s_cv[row * 32 + sb]     = t1v[ri]; s_ci[row * 32 + sb]     = t1i[ri];
                s_cv[row * 32 + sb + 1] = t2v[ri]; s_ci[row * 32 + sb + 1] = t2i[ri];
            }
        __syncthreads();

        // ---- approx top-8 prefilter per row (into slots 0..7) ----
        if (tid < MC) {
            float bv[8]; int bi[8];
#pragma unroll
            for (int t = 0; t < 8; t++) { bv[t] = -3.0e38f; bi[t] = 0x7fffffff; }
            for (int t = 0; t < 32; t++) {
                float v = s_cv[tid * 32 + t]; int ix = s_ci[tid * 32 + t];
                if (v > bv[7]) {
#pragma unroll
                    for (int q = 0; q < 8; q++) {
                        if (v > bv[q]) {
                            const float a = bv[q]; const int b2 = bi[q];
                            bv[q] = v; bi[q] = ix; v = a; ix = b2;
                        }
                    }
                }
            }
#pragma unroll
            for (int t = 0; t < 8; t++) {
                s_cv[tid * 32 + t] = bv[t]; s_ci[tid * 32 + t] = bi[t];
            }
        }
        __syncthreads();

        // ---- exact fp32 rescore: 64 rows x 8 cands, 64 dots per warp ----
        for (int i = 0; i < 64; i++) {
            const int p    = warp * 64 + i;
            const int row  = p >> 3, slot = p & 7;
            const int cand = s_ci[row * 32 + slot] & (KS - 1);   // masked: no OOB ever
            const float4* rr = reinterpret_cast<const float4*>(g_res + (row0 + row) * DIM);
            const float4* cc = reinterpret_cast<const float4*>(cb + (size_t)cand * DIM);
            float sum = 0.0f;
#pragma unroll
            for (int q = 0; q < 4; q++) {
                const float4 a = rr[lane + 32 * q];
                const float4 b2 = cc[lane + 32 * q];
                sum += a.x * b2.x + a.y * b2.y + a.z * b2.z + a.w * b2.w;
            }
#pragma unroll
            for (int off = 16; off; off >>= 1)
                sum += __shfl_xor_sync(0xffffffffu, sum, off);
            if (lane == 0) s_cv[row * 32 + slot] = sum;   // exact value
        }
        __syncthreads();

        // ---- winner per row (tie: lowest index) + update (8 rows/warp) ----
        __shared__ float s_u[MC];
        __shared__ int   s_code[MC];
        if (tid < MC) {
            float bv = s_cv[tid * 32]; int bi = s_ci[tid * 32];
#pragma unroll
            for (int t = 1; t < 8; t++) {
                const float v = s_cv[tid * 32 + t]; const int ix = s_ci[tid * 32 + t];
                if (v > bv || (v == bv && ix < bi)) { bv = v; bi = ix; }
            }
            s_u[tid] = bv; s_code[tid] = bi & (KS - 1);
        }
        __syncthreads();

        // ---- residual update (fp32 global) + bf16 A refill (8 rows/warp) ----
        for (int rr = 0; rr < MC / NWARP; rr++) {
            const int r = warp * (MC / NWARP) + rr;
            const float uv = s_u[r];
            const int code = s_code[r];
            float4* dres = reinterpret_cast<float4*>(g_res + (row0 + r) * DIM);
            const float4* cc = reinterpret_cast<const float4*>(cb + (size_t)code * DIM);
#pragma unroll
            for (int q = 0; q < 2; q++) {
                const int c = lane + 32 * q;            // 16B chunk index
                float4 v0 = dres[c * 2 + 0], v1 = dres[c * 2 + 1];
                const float4 c0 = cc[c * 2 + 0], c1 = cc[c * 2 + 1];
                v0.x -= uv * c0.x; v0.y -= uv * c0.y; v0.z -= uv * c0.z; v0.w -= uv * c0.w;
                v1.x -= uv * c1.x; v1.y -= uv * c1.y; v1.z -= uv * c1.z; v1.w -= uv * c1.w;
                dres[c * 2 + 0] = v0; dres[c * 2 + 1] = v1;
                uint4 pk;
                pk.x = pack_bf2(v0.x, v0.y); pk.y = pack_bf2(v0.z, v0.w);
                pk.z = pack_bf2(v1.x, v1.y); pk.w = pack_bf2(v1.z, v1.w);
                *reinterpret_cast<uint4*>(sAp + r * 1024 + ((c ^ (r & 7)) << 4)) = pk;
            }
        }
        __syncthreads();
    }

    // ---- output: total = x - residual_final ----
    const float4* x4 = reinterpret_cast<const float4*>(x + row0 * DIM);
    const float4* r4 = reinterpret_cast<const float4*>(g_res + row0 * DIM);
    float4* o4 = reinterpret_cast<float4*>(out + row0 * DIM);
    for (int i = tid; i < MC * DIM / 4; i += THREADS) {
        const float4 xv = x4[i];
        const float4 rv = r4[i];
        o4[i] = make_float4(xv.x - rv.x, xv.y - rv.y, xv.z - rv.z, xv.w - rv.w);
    }
}

// ---------------------------------------------------------------------------
extern "C" void kernel_launch(void* const* d_in, const int* in_sizes, int n_in,
                              void* d_out, int out_size) {
    const float* x  = (const float*)d_in[0];
    const float* cb = (const float*)d_in[1];
    const int* depth_ptr = (n_in > 2) ? (const int*)d_in[2] : nullptr;
    float* out = (float*)d_out;

    const int dyn_smem = A_BYTES + NBUF * BTILE_BYTES;   // 65536 + 49152 = 114688
    cudaFuncSetAttribute(rvq_mma_kernel, cudaFuncAttributeMaxDynamicSharedMemorySize,
                         dyn_smem);

    pack_cb_kernel<<<(KS * DIM / 4) / 256, 256>>>(cb);
    rvq_mma_kernel<<<NTOK / MC, THREADS, dyn_smem>>>(x, cb, depth_ptr, out);
}

// round 17
// speedup vs baseline: 1.6798x; 1.6798x over previous
#include <cuda_runtime.h>
#include <cuda_bf16.h>
#include <cstdint>
#include <cstddef>

// Residual VQ, round 17: Gram-matrix recurrence. ip_{d+1} = ip_d - u_d * G[code_d]
// with G = C C^T, so only depth 0 runs a GEMM (R13's proven kernel + bf16 ip
// store); depths 1.. are streaming row updates (bandwidth-bound) with the same
// top-8 + exact-fp32-rescore rescue against the exactly-maintained residual.

#define NTOK     16384
#define DIM      512
#define KS       4096
#define MC       128
#define THREADS  512
#define NWARP    16
#define BN       256
#define BK       64
#define NTILES   (KS / BN)          // 16
#define NCHUNK   (DIM / BK)         // 8
#define UNITS    (NTILES * NCHUNK)  // 128
#define BTILE_BYTES (BN * BK * 2)   // 32768
#define NBUF     3
#define A_BYTES  (MC * DIM * 2)     // 131072
#define KSU      (KS / 2)           // 2048 uints (bf16x2) per ip row

__device__ float         g_res[(size_t)NTOK * DIM];     // fp32 residual master
__device__ __nv_bfloat16 g_cbh[(size_t)KS * DIM];       // bf16 codebook
__device__ float         g_gram[(size_t)KS * KS];       // fp32 Gram, 64MB
__device__ uint32_t      g_ip[(size_t)NTOK * KSU];      // bf16x2 ip, 128MB
__device__ float         g_u[NTOK];
__device__ int           g_code[NTOK];

// ---------------------------------------------------------------------------
static __device__ __forceinline__ uint32_t smem_u32(const void* p) {
    return (uint32_t)__cvta_generic_to_shared(p);
}
static __device__ __forceinline__ void ldsm4(uint32_t* r, uint32_t a) {
    asm volatile("ldmatrix.sync.aligned.m8n8.x4.shared.b16 {%0,%1,%2,%3}, [%4];"
                 : "=r"(r[0]), "=r"(r[1]), "=r"(r[2]), "=r"(r[3]) : "r"(a));
}
static __device__ __forceinline__ void mma16816(float* c, const uint32_t* a,
                                                const uint32_t* b) {
    asm volatile("mma.sync.aligned.m16n8k16.row.col.f32.bf16.bf16.f32 "
                 "{%0,%1,%2,%3}, {%4,%5,%6,%7}, {%8,%9}, {%0,%1,%2,%3};"
                 : "+f"(c[0]), "+f"(c[1]), "+f"(c[2]), "+f"(c[3])
                 : "r"(a[0]), "r"(a[1]), "r"(a[2]), "r"(a[3]),
                   "r"(b[0]), "r"(b[1]));
}
static __device__ __forceinline__ void cp16(uint32_t dst, const void* src) {
    asm volatile("cp.async.cg.shared.global [%0], [%1], 16;" :: "r"(dst), "l"(src));
}
static __device__ __forceinline__ void mbar_init(uint32_t a, uint32_t cnt) {
    asm volatile("mbarrier.init.shared.b64 [%0], %1;" :: "r"(a), "r"(cnt) : "memory");
}
static __device__ __forceinline__ void mbar_arrive(uint32_t a) {
    asm volatile("mbarrier.arrive.shared.b64 _, [%0];" :: "r"(a) : "memory");
}
static __device__ __forceinline__ void cpasync_mbar_arrive(uint32_t a) {
    asm volatile("cp.async.mbarrier.arrive.noinc.shared.b64 [%0];" :: "r"(a) : "memory");
}
static __device__ __forceinline__ void mbar_wait(uint32_t a, uint32_t parity) {
    uint32_t done;
    asm volatile("{\n\t.reg .pred p;\n\t"
                 "mbarrier.try_wait.parity.acquire.cta.shared::cta.b64 p, [%1], %2;\n\t"
                 "selp.b32 %0, 1, 0, p;\n\t}"
                 : "=r"(done) : "r"(a), "r"(parity) : "memory");
    if (!done) {
        asm volatile("{\n\t.reg .pred P1;\n\t"
                     "WL%=:\n\t"
                     "mbarrier.try_wait.parity.acquire.cta.shared::cta.b64 P1, [%0], %1, 0x989680;\n\t"
                     "@P1 bra.uni WD%=;\n\tbra.uni WL%=;\n\tWD%=:\n\t}"
                     :: "r"(a), "r"(parity) : "memory");
    }
}
static __device__ __forceinline__ uint32_t pack_bf2(float a, float b) {
    __nv_bfloat162 h = __floats2bfloat162_rn(a, b);
    return *reinterpret_cast<uint32_t*>(&h);
}
static __device__ __forceinline__ float2 unpack_bf2(uint32_t u) {
    __nv_bfloat162 h = *reinterpret_cast<__nv_bfloat162*>(&u);
    return make_float2(__bfloat162float(h.x), __bfloat162float(h.y));
}
static __device__ __forceinline__ int read_depth(const int* p) {
    int depth = 4;
    if (p) { const int dd = *p; if (dd >= 0 && dd <= 8) depth = dd; }
    return depth;
}

// ---------------------------------------------------------------------------
__global__ void pack_cb_kernel(const float* __restrict__ cb) {
    const size_t i = ((size_t)blockIdx.x * 256 + threadIdx.x) * 4;
    const float4 v = *reinterpret_cast<const float4*>(cb + i);
    uint2 o;
    o.x = pack_bf2(v.x, v.y);
    o.y = pack_bf2(v.z, v.w);
    *reinterpret_cast<uint2*>(&g_cbh[i]) = o;
}

// ---------------------------------------------------------------------------
// Gram: G[i][j] = cb_i . cb_j (fp32 out). grid (32,32) x 512 thr.
// Warp geometry copied verbatim from the correctness-validated R16 mainloop.
// smem: A 128KB (i-rows, swizzled 1KB rows) + B 16KB single buffer.
// ---------------------------------------------------------------------------
__global__ void __launch_bounds__(512, 1)
gram_kernel(const int* __restrict__ depth_ptr) {
    if (read_depth(depth_ptr) < 2) return;   // G unused when depth <= 1
    extern __shared__ __align__(1024) unsigned char raw[];
    unsigned char* sAp = raw;
    unsigned char* sBp = raw + A_BYTES;
    const uint32_t sA = smem_u32(sAp);
    const uint32_t sB = smem_u32(sBp);

    const int tid  = threadIdx.x;
    const int warp = tid >> 5;
    const int lane = tid & 31;
    const int wm   = warp >> 2;
    const int wn   = warp & 3;
    const int i0 = blockIdx.y * 128;
    const int j0 = blockIdx.x * 128;

    for (int e = tid; e < 128 * 64; e += 512) {
        const int row = e >> 6, c = e & 63;
        const uint4 v = *reinterpret_cast<const uint4*>(
            g_cbh + (size_t)(i0 + row) * DIM + c * 8);
        *reinterpret_cast<uint4*>(sAp + row * 1024 + ((c ^ (row & 7)) << 4)) = v;
    }

    const int lm = lane & 15, lh = lane >> 4;
    const int axor = lm & 7;
    uint32_t cAm[2];
#pragma unroll
    for (int mi = 0; mi < 2; mi++)
        cAm[mi] = sA + (uint32_t)(wm * 32 + mi * 16 + lm) * 1024;
    const int grp = lane >> 3, lrow = lane & 7, kpar = grp & 1;
    const int rowoff = ((grp >> 1) << 3) + lrow;
    const int bxor = lrow;

    float acc[2][4][4];
#pragma unroll
    for (int mi = 0; mi < 2; mi++)
#pragma unroll
        for (int ni = 0; ni < 4; ni++)
#pragma unroll
            for (int j = 0; j < 4; j++) acc[mi][ni][j] = 0.0f;

    for (int kc = 0; kc < 8; kc++) {
        __syncthreads();
        for (int i = 0; i < 2; i++) {
            const int e = tid + 512 * i;      // 1024 chunks: 128 rows x 8
            const int rowb = e >> 3, c = e & 7;
            const uint4 v = *reinterpret_cast<const uint4*>(
                g_cbh + (size_t)(j0 + rowb) * DIM + kc * 64 + c * 8);
            *reinterpret_cast<uint4*>(sBp + rowb * 128 + ((c ^ (rowb & 7)) << 4)) = v;
        }
        __syncthreads();

        uint32_t cBn[2];
#pragma unroll
        for (int nb = 0; nb < 2; nb++)
            cBn[nb] = sB + (uint32_t)(wn * 32 + nb * 16 + rowoff) * 128;
#pragma unroll
        for (int ks = 0; ks < 4; ks++) {
            uint32_t a[2][4], bfr[2][4];
            const int ck = kc * 8 + ks * 2 + lh;
            const uint32_t aoff = (uint32_t)((ck ^ axor) << 4);
#pragma unroll
            for (int mi = 0; mi < 2; mi++) ldsm4(a[mi], cAm[mi] + aoff);
            const uint32_t boff = (uint32_t)(((ks * 2 + kpar) ^ bxor) << 4);
#pragma unroll
            for (int nb = 0; nb < 2; nb++) ldsm4(bfr[nb], cBn[nb] + boff);
#pragma unroll
            for (int mi = 0; mi < 2; mi++)
#pragma unroll
                for (int nb = 0; nb < 2; nb++) {
                    mma16816(acc[mi][nb * 2 + 0], a[mi], bfr[nb] + 0);
                    mma16816(acc[mi][nb * 2 + 1], a[mi], bfr[nb] + 2);
                }
        }
    }

#pragma unroll
    for (int mi = 0; mi < 2; mi++)
#pragma unroll
        for (int rh = 0; rh < 2; rh++) {
            const int row = i0 + wm * 32 + mi * 16 + rh * 8 + (lane >> 2);
#pragma unroll
            for (int ni = 0; ni < 4; ni++)
#pragma unroll
                for (int j = 0; j < 2; j++) {
                    const int col = j0 + wn * 32 + ni * 8 + 2 * (lane & 3) + j;
                    g_gram[(size_t)row * KS + col] = acc[mi][ni][rh * 2 + j];
                }
        }
}

// ---------------------------------------------------------------------------
// Depth-0: R13's GEMM + bf16 ip store + top-8 exact-rescore tail.
// grid 128 x 512 thr; dyn smem A 128KB + 3x32KB ring.
// ---------------------------------------------------------------------------
__global__ void __launch_bounds__(THREADS, 1)
d0_kernel(const float* __restrict__ x, const float* __restrict__ cb,
          const int* __restrict__ depth_ptr) {
    extern __shared__ __align__(1024) unsigned char raw[];
    unsigned char* sAp = raw;
    const uint32_t sA  = smem_u32(sAp);
    const uint32_t sB0 = smem_u32(raw + A_BYTES);

    __shared__ __align__(8) unsigned long long s_mbar[6];

    const int tid  = threadIdx.x;
    const int warp = tid >> 5;
    const int lane = tid & 31;
    const int wm   = warp >> 2;
    const int wn   = warp & 3;
    const size_t row0 = (size_t)blockIdx.x * MC;

    uint32_t mb_full[3], mb_empty[3];
#pragma unroll
    for (int b = 0; b < 3; b++) {
        mb_full[b]  = smem_u32(&s_mbar[b]);
        mb_empty[b] = smem_u32(&s_mbar[3 + b]);
    }

    const int depth = read_depth(depth_ptr);

    if (tid == 0) {
#pragma unroll
        for (int b = 0; b < 3; b++) {
            mbar_init(mb_full[b], THREADS);
            mbar_init(mb_empty[b], NWARP);
        }
    }

    // residual = x; bf16 A tile in smem
    for (int e = tid; e < MC * 64; e += THREADS) {
        const int row = e >> 6, c = e & 63;
        const float4* src = reinterpret_cast<const float4*>(x + (row0 + row) * DIM + c * 8);
        const float4 v0 = src[0], v1 = src[1];
        float4* dres = reinterpret_cast<float4*>(g_res + (row0 + row) * DIM + c * 8);
        dres[0] = v0; dres[1] = v1;
        uint4 pk;
        pk.x = pack_bf2(v0.x, v0.y); pk.y = pack_bf2(v0.z, v0.w);
        pk.z = pack_bf2(v1.x, v1.y); pk.w = pack_bf2(v1.z, v1.w);
        *reinterpret_cast<uint4*>(sAp + row * 1024 + ((c ^ (row & 7)) << 4)) = pk;
    }
    __syncthreads();
    if (depth < 1) return;

    auto fillg = [&](int G) {
        const int b2 = G % NBUF;
        const int r2 = G / NBUF;
        mbar_wait(mb_empty[b2], (uint32_t)((r2 & 1) ^ 1));
        const int nt = G >> 3, kc = G & 7;
        const uint32_t dst = sB0 + (uint32_t)b2 * BTILE_BYTES;
        const __nv_bfloat16* src = g_cbh + (size_t)(nt * BN) * DIM + kc * BK;
#pragma unroll
        for (int i = 0; i < 4; i++) {
            const int e = tid + THREADS * i;
            const int rowb = e >> 3, c = e & 7;
            cp16(dst + rowb * 128 + ((c ^ (rowb & 7)) << 4),
                 src + (size_t)rowb * DIM + c * 8);
        }
        cpasync_mbar_arrive(mb_full[b2]);
    };
    fillg(0);
    fillg(1);

    const int lm = lane & 15, lh = lane >> 4;
    const int axor = lm & 7;
    uint32_t cAm[2];
#pragma unroll
    for (int mi = 0; mi < 2; mi++)
        cAm[mi] = sA + (uint32_t)(wm * 32 + mi * 16 + lm) * 1024;
    const int grp = lane >> 3, lrow = lane & 7, kpar = grp & 1;
    const int rowoff = ((grp >> 1) << 3) + lrow;
    const int bxor = lrow;

    float acc[2][8][4];
#pragma unroll
    for (int mi = 0; mi < 2; mi++)
#pragma unroll
        for (int ni = 0; ni < 8; ni++)
#pragma unroll
            for (int j = 0; j < 4; j++) acc[mi][ni][j] = 0.0f;

    float t1v[4], t2v[4]; int t1i[4], t2i[4];
#pragma unroll
    for (int r = 0; r < 4; r++) {
        t1v[r] = -3.0e38f; t2v[r] = -3.0e38f;
        t1i[r] = 0x7fffffff; t2i[r] = 0x7fffffff;
    }

    for (int u = 0; u < UNITS; u++) {
        const int b  = u % NBUF;
        const int nt = u >> 3, kc = u & 7;
        mbar_wait(mb_full[b], (uint32_t)((u / NBUF) & 1));

        const uint32_t sB = sB0 + (uint32_t)b * BTILE_BYTES;
        uint32_t cBn[4];
#pragma unroll
        for (int nb = 0; nb < 4; nb++)
            cBn[nb] = sB + (uint32_t)(wn * 64 + nb * 16 + rowoff) * 128;

#pragma unroll
        for (int ks = 0; ks < 4; ks++) {
            uint32_t a[2][4], bfr[4][4];
            const int ck = kc * 8 + ks * 2 + lh;
            const uint32_t aoff = (uint32_t)((ck ^ axor) << 4);
#pragma unroll
            for (int mi = 0; mi < 2; mi++) ldsm4(a[mi], cAm[mi] + aoff);
            const uint32_t boff = (uint32_t)(((ks * 2 + kpar) ^ bxor) << 4);
#pragma unroll
            for (int nb = 0; nb < 4; nb++) ldsm4(bfr[nb], cBn[nb] + boff);
#pragma unroll
            for (int mi = 0; mi < 2; mi++)
#pragma unroll
                for (int nb = 0; nb < 4; nb++) {
                    mma16816(acc[mi][nb * 2 + 0], a[mi], bfr[nb] + 0);
                    mma16816(acc[mi][nb * 2 + 1], a[mi], bfr[nb] + 2);
                }
        }

        if (lane == 0) mbar_arrive(mb_empty[b]);

        if (kc == NCHUNK - 1) {
            const int cb0 = nt * BN + wn * 64 + 2 * (lane & 3);
#pragma unroll
            for (int mi = 0; mi < 2; mi++)
#pragma unroll
                for (int rh = 0; rh < 2; rh++) {
                    const int ri = mi * 2 + rh;
                    const int row = wm * 32 + mi * 16 + rh * 8 + (lane >> 2);
                    uint32_t* iprow = g_ip + (row0 + row) * KSU + (cb0 >> 1);
#pragma unroll
                    for (int ni = 0; ni < 8; ni++) {
                        // store bf16 ip pair (cols cb0+ni*8, +1)
                        iprow[ni * 4] = pack_bf2(acc[mi][ni][rh * 2 + 0],
                                                 acc[mi][ni][rh * 2 + 1]);
#pragma unroll
                        for (int j = 0; j < 2; j++) {
                            const float v = acc[mi][ni][rh * 2 + j];
                            const int  ix = cb0 + ni * 8 + j;
                            if (v > t1v[ri]) {
                                t2v[ri] = t1v[ri]; t2i[ri] = t1i[ri];
                                t1v[ri] = v;       t1i[ri] = ix;
                            } else if (v > t2v[ri]) {
                                t2v[ri] = v; t2i[ri] = ix;
                            }
                        }
                    }
#pragma unroll
                    for (int ni = 0; ni < 8; ni++) {
                        acc[mi][ni][rh * 2 + 0] = 0.0f;
                        acc[mi][ni][rh * 2 + 1] = 0.0f;
                    }
                }
        }

        const int G2 = u + 2;
        if (G2 < UNITS) fillg(G2);
    }

    __syncthreads();

    float* s_cv = reinterpret_cast<float*>(raw + A_BYTES);
    int*   s_ci = reinterpret_cast<int*>(raw + A_BYTES + 16384);

#pragma unroll
    for (int mi = 0; mi < 2; mi++)
#pragma unroll
        for (int rh = 0; rh < 2; rh++) {
            const int ri  = mi * 2 + rh;
            const int row = wm * 32 + mi * 16 + rh * 8 + (lane >> 2);
            const int sb  = wn * 8 + (lane & 3) * 2;
            s_cv[row * 32 + sb]     = t1v[ri]; s_ci[row * 32 + sb]     = t1i[ri];
            s_cv[row * 32 + sb + 1] = t2v[ri]; s_ci[row * 32 + sb + 1] = t2i[ri];
        }
    __syncthreads();

    if (tid < MC) {
        float bv[8]; int bi[8];
#pragma unroll
        for (int t = 0; t < 8; t++) { bv[t] = -3.0e38f; bi[t] = 0x7fffffff; }
        for (int t = 0; t < 32; t++) {
            float v = s_cv[tid * 32 + t]; int ix = s_ci[tid * 32 + t];
            if (v > bv[7]) {
#pragma unroll
                for (int q = 0; q < 8; q++) {
                    if (v > bv[q]) {
                        const float a = bv[q]; const int b2 = bi[q];
                        bv[q] = v; bi[q] = ix; v = a; ix = b2;
                    }
                }
            }
        }
#pragma unroll
        for (int t = 0; t < 8; t++) {
            s_cv[tid * 32 + t] = bv[t]; s_ci[tid * 32 + t] = bi[t];
        }
    }
    __syncthreads();

    for (int i = 0; i < 64; i++) {
        const int p    = warp * 64 + i;
        const int row  = p >> 3, slot = p & 7;
        const int cand = s_ci[row * 32 + slot] & (KS - 1);
        const float4* rr = reinterpret_cast<const float4*>(g_res + (row0 + row) * DIM);
        const float4* cc = reinterpret_cast<const float4*>(cb + (size_t)cand * DIM);
        float sum = 0.0f;
#pragma unroll
        for (int q = 0; q < 4; q++) {
            const float4 a = rr[lane + 32 * q];
            const float4 b2 = cc[lane + 32 * q];
            sum += a.x * b2.x + a.y * b2.y + a.z * b2.z + a.w * b2.w;
        }
#pragma unroll
        for (int off = 16; off; off >>= 1)
            sum += __shfl_xor_sync(0xffffffffu, sum, off);
        if (lane == 0) s_cv[row * 32 + slot] = sum;
    }
    __syncthreads();

    __shared__ float s_u[MC];
    __shared__ int   s_code[MC];
    if (tid < MC) {
        float bv = s_cv[tid * 32]; int bi = s_ci[tid * 32];
#pragma unroll
        for (int t = 1; t < 8; t++) {
            const float v = s_cv[tid * 32 + t]; const int ix = s_ci[tid * 32 + t];
            if (v > bv || (v == bv && ix < bi)) { bv = v; bi = ix; }
        }
        s_u[tid] = bv; s_code[tid] = bi & (KS - 1);
        g_u[row0 + tid]    = bv;
        g_code[row0 + tid] = bi & (KS - 1);
    }
    __syncthreads();

    for (int rr = 0; rr < MC / NWARP; rr++) {
        const int r = warp * (MC / NWARP) + rr;
        const float uv = s_u[r];
        const int code = s_code[r];
        float4* dres = reinterpret_cast<float4*>(g_res + (row0 + r) * DIM);
        const float4* cc = reinterpret_cast<const float4*>(cb + (size_t)code * DIM);
#pragma unroll
        for (int q = 0; q < 4; q++) {
            const int idx = lane + 32 * q;
            float4 v = dres[idx];
            const float4 c = cc[idx];
            v.x -= uv * c.x; v.y -= uv * c.y; v.z -= uv * c.z; v.w -= uv * c.w;
            dres[idx] = v;
        }
    }
}

// ---------------------------------------------------------------------------
// Depth d>=1: ip -= u_prev * G[code_prev]; top-2/lane -> top-8 -> exact
// rescore vs g_res -> winner -> residual update; writes u/code for next depth.
// grid 2048 x 256 thr; warp w owns row blockIdx.x*8 + w.
// ---------------------------------------------------------------------------
__global__ void __launch_bounds__(256, 4)
update_kernel(const float* __restrict__ cb, const int* __restrict__ depth_ptr,
              int d_idx) {
    if (d_idx >= read_depth(depth_ptr)) return;

    __shared__ float s_cv[8][64];
    __shared__ int   s_ci[8][64];

    const int tid  = threadIdx.x;
    const int warp = tid >> 5;
    const int lane = tid & 31;
    const size_t r = (size_t)blockIdx.x * 8 + warp;

    const float up   = g_u[r];
    const int   code = g_code[r];
    const float4* Gr = reinterpret_cast<const float4*>(g_gram + (size_t)code * KS);
    uint4* ipr = reinterpret_cast<uint4*>(g_ip + r * KSU);

    float v1 = -3.0e38f, v2 = -3.0e38f;
    int   i1 = 0x7fffffff, i2 = 0x7fffffff;

#pragma unroll 4
    for (int it = 0; it < 16; it++) {
        const int idx4 = lane + 32 * it;        // uint4 index, 8 bf16 each
        uint4 ipq = ipr[idx4];
        const float4 ga = Gr[idx4 * 2];
        const float4 gb = Gr[idx4 * 2 + 1];
        float2 p0 = unpack_bf2(ipq.x), p1 = unpack_bf2(ipq.y);
        float2 p2 = unpack_bf2(ipq.z), p3 = unpack_bf2(ipq.w);
        p0.x -= up * ga.x; p0.y -= up * ga.y;
        p1.x -= up * ga.z; p1.y -= up * ga.w;
        p2.x -= up * gb.x; p2.y -= up * gb.y;
        p3.x -= up * gb.z; p3.y -= up * gb.w;
        const int c0 = idx4 * 8;
        const float vals[8] = {p0.x, p0.y, p1.x, p1.y, p2.x, p2.y, p3.x, p3.y};
#pragma unroll
        for (int k = 0; k < 8; k++) {
            const float v = vals[k];
            if (v > v1)      { v2 = v1; i2 = i1; v1 = v; i1 = c0 + k; }
            else if (v > v2) { v2 = v;  i2 = c0 + k; }
        }
        ipq.x = pack_bf2(p0.x, p0.y); ipq.y = pack_bf2(p1.x, p1.y);
        ipq.z = pack_bf2(p2.x, p2.y); ipq.w = pack_bf2(p3.x, p3.y);
        ipr[idx4] = ipq;
    }

    s_cv[warp][lane]      = v1; s_ci[warp][lane]      = i1;
    s_cv[warp][lane + 32] = v2; s_ci[warp][lane + 32] = i2;
    __syncthreads();

    // prefilter top-8 per row (one thread per row)
    if (tid < 8) {
        float bv[8]; int bi[8];
#pragma unroll
        for (int t = 0; t < 8; t++) { bv[t] = -3.0e38f; bi[t] = 0x7fffffff; }
        for (int t = 0; t < 64; t++) {
            float v = s_cv[tid][t]; int ix = s_ci[tid][t];
            if (v > bv[7]) {
#pragma unroll
                for (int q = 0; q < 8; q++) {
                    if (v > bv[q]) {
                        const float a = bv[q]; const int b2 = bi[q];
                        bv[q] = v; bi[q] = ix; v = a; ix = b2;
                    }
                }
            }
        }
#pragma unroll
        for (int t = 0; t < 8; t++) s_ci[tid][t] = bi[t];
    }
    __syncthreads();

    // fused exact rescore + winner + residual update (warp owns its row)
    const float4* rrp = reinterpret_cast<const float4*>(g_res + r * DIM);
    float4 ra[4];
#pragma unroll
    for (int q = 0; q < 4; q++) ra[q] = rrp[lane + 32 * q];

    float ex[8];
#pragma unroll 1
    for (int slot = 0; slot < 8; slot++) {
        const int cand = s_ci[warp][slot] & (KS - 1);
        const float4* cc = reinterpret_cast<const float4*>(cb + (size_t)cand * DIM);
        float sum = 0.0f;
#pragma unroll
        for (int q = 0; q < 4; q++) {
            const float4 b2 = cc[lane + 32 * q];
            sum += ra[q].x * b2.x + ra[q].y * b2.y + ra[q].z * b2.z + ra[q].w * b2.w;
        }
#pragma unroll
        for (int off = 16; off; off >>= 1)
            sum += __shfl_xor_sync(0xffffffffu, sum, off);
        ex[slot] = sum;
    }

    float bv = ex[0]; int bi = s_ci[warp][0] & (KS - 1);
#pragma unroll
    for (int t = 1; t < 8; t++) {
        const float v = ex[t]; const int ix = s_ci[warp][t] & (KS - 1);
        if (v > bv || (v == bv && ix < bi)) { bv = v; bi = ix; }
    }

    const float4* cw = reinterpret_cast<const float4*>(cb + (size_t)bi * DIM);
    float4* wrp = reinterpret_cast<float4*>(g_res + r * DIM);
#pragma unroll
    for (int q = 0; q < 4; q++) {
        const int idx = lane + 32 * q;
        const float4 c = cw[idx];
        float4 v = ra[q];
        v.x -= bv * c.x; v.y -= bv * c.y; v.z -= bv * c.z; v.w -= bv * c.w;
        wrp[idx] = v;
    }
    if (lane == 0) { g_u[r] = bv; g_code[r] = bi; }
}

// ---------------------------------------------------------------------------
__global__ void out_kernel(const float* __restrict__ x, float* __restrict__ out) {
    const size_t i = (size_t)blockIdx.x * 256 + threadIdx.x;
    const float4 xv = reinterpret_cast<const float4*>(x)[i];
    const float4 rv = reinterpret_cast<const float4*>(g_res)[i];
    reinterpret_cast<float4*>(out)[i] =
        make_float4(xv.x - rv.x, xv.y - rv.y, xv.z - rv.z, xv.w - rv.w);
}

// ---------------------------------------------------------------------------
extern "C" void kernel_launch(void* const* d_in, const int* in_sizes, int n_in,
                              void* d_out, int out_size) {
    const float* x  = (const float*)d_in[0];
    const float* cb = (const float*)d_in[1];
    const int* depth_ptr = (n_in > 2) ? (const int*)d_in[2] : nullptr;
    float* out = (float*)d_out;

    const int smem_d0   = A_BYTES + NBUF * BTILE_BYTES;  // 229376
    const int smem_gram = A_BYTES + 16384;               // 147456
    cudaFuncSetAttribute(d0_kernel, cudaFuncAttributeMaxDynamicSharedMemorySize, smem_d0);
    cudaFuncSetAttribute(gram_kernel, cudaFuncAttributeMaxDynamicSharedMemorySize, smem_gram);

    pack_cb_kernel<<<(KS * DIM / 4) / 256, 256>>>(cb);
    gram_kernel<<<dim3(KS / 128, KS / 128), 512, smem_gram>>>(depth_ptr);
    d0_kernel<<<NTOK / MC, THREADS, smem_d0>>>(x, cb, depth_ptr);
    for (int d = 1; d < 8; d++)
        update_kernel<<<NTOK / 8, 256>>>(cb, depth_ptr, d);
    out_kernel<<<NTOK * DIM / 4 / 256, 256>>>(x, out);
}